// round 13
// baseline (speedup 1.0000x reference)
#include <cuda_runtime.h>
#include <cuda_bf16.h>

// DWT_1D via polyphase, 2 blocks per row (half-row each) for finer waves,
// smaller barrier scope, and better DRAM latency overlap.
//   lo[k] = h0*xo[k-2]+h2*xo[k-1]+h4*xo[k]+h6*xo[k+1]
//         + h1*xe[k-1]+h3*xe[k]+h5*xe[k+1]+h7*xe[k+2]
//   hi[k] = h7*xo[k-2]+h5*xo[k-1]+h3*xo[k]+h1*xo[k+1]
//         - h6*xe[k-1]-h4*xe[k]-h2*xe[k+1]-h0*xe[k+2]
// (REC_HI[j] = (-1)^j REC_LO[7-j] bit-exact -> hi reuses the lo taps.)
// All gmem/smem accesses lane-contiguous.

namespace {
constexpr int SEQ   = 8192;
constexpr int KOUT  = 4096;
constexpr int NC    = 16 * 64;        // 1024 rows
constexpr int TPB   = 256;
constexpr int KHALF = KOUT / 2;       // 2048 outputs per block
constexpr int NP    = KHALF + 8;      // per-phase smem floats (pad 2 front, 6 back)
constexpr int S4    = SEQ / 4;        // 2048 float4 per row
}

__global__ __launch_bounds__(TPB, 5)
void dwt1d_kernel(const float4* __restrict__ x4,
                  const float* __restrict__ mlo,
                  const float* __restrict__ mhi,
                  float* __restrict__ out)
{
    // pe_s[j] = xe[K0-2+j], po_s[j] = xo[K0-2+j], j = 0..NP-1
    __shared__ alignas(16) float pe_s[NP];
    __shared__ alignas(16) float po_s[NP];

    const int row  = blockIdx.x >> 1;
    const int half = blockIdx.x & 1;
    const int K0   = half * KHALF;         // first output k of this block
    const int tid  = threadIdx.x;

    // Stage + deinterleave. Need float4 f in [K0/2 - 1, K0/2 + 1026] (1028 of them).
    // Out-of-range f -> zeros (covers row-edge pads automatically).
    {
        const float4* __restrict__ xr = x4 + (size_t)row * S4;
        float2* __restrict__ pe2 = reinterpret_cast<float2*>(pe_s);
        float2* __restrict__ po2 = reinterpret_cast<float2*>(po_s);
        const int f0 = K0 / 2 - 1;
        #pragma unroll
        for (int i = 0; i < 5; ++i) {
            const int q = tid + i * TPB;          // 0..1279, need 0..1027
            if (i < 4 || q < 1028) {
                const int f = f0 + q;
                float4 v = (f >= 0 && f < S4) ? xr[f] : make_float4(0.f, 0.f, 0.f, 0.f);
                pe2[q] = make_float2(v.x, v.z);   // xe[2f], xe[2f+1]
                po2[q] = make_float2(v.y, v.w);   // xo[2f], xo[2f+1]
            }
        }
    }

    // Low-pass taps (hi derived); row 2, cols 1..8 of the banded matrix.
    float h[8];
    #pragma unroll
    for (int j = 0; j < 8; ++j) h[j] = __ldg(&mlo[2 * SEQ + 1 + j]);

    __syncthreads();

    const float4* __restrict__ pe4 = reinterpret_cast<const float4*>(pe_s);
    const float4* __restrict__ po4 = reinterpret_cast<const float4*>(po_s);
    float4* __restrict__ lo4 = reinterpret_cast<float4*>(out + (size_t)row * KOUT + K0);
    float4* __restrict__ hi4 = reinterpret_cast<float4*>(out + (size_t)NC * KOUT + (size_t)row * KOUT + K0);

    #pragma unroll
    for (int it = 0; it < KHALF / 4 / TPB; ++it) {   // 2 iters
        const int t = tid + it * TPB;                // local group; outputs k = K0+4t..+3

        // o[m] = xo[K0+4t-2+m] = po_s[4t+m]; e[m] likewise. 2 LDS.128 each.
        float4 o0 = po4[t];
        float4 o1 = po4[t + 1];
        float4 e0 = pe4[t];
        float4 e1 = pe4[t + 1];
        const float o[8] = { o0.x, o0.y, o0.z, o0.w, o1.x, o1.y, o1.z, o1.w };
        const float e[8] = { e0.x, e0.y, e0.z, e0.w, e1.x, e1.y, e1.z, e1.w };

        float lo[4], hi[4];
        #pragma unroll
        for (int d = 0; d < 4; ++d) {
            float s0 = fmaf(h[0], o[d+0], h[1] * e[d+1]);
            s0 = fmaf(h[2], o[d+1], s0);
            s0 = fmaf(h[3], e[d+2], s0);
            s0 = fmaf(h[4], o[d+2], s0);
            s0 = fmaf(h[5], e[d+3], s0);
            s0 = fmaf(h[6], o[d+3], s0);
            s0 = fmaf(h[7], e[d+4], s0);
            lo[d] = s0;

            float s1 = fmaf(h[7], o[d+0], h[6] * (-e[d+1]));
            s1 = fmaf(h[5], o[d+1], s1);
            s1 = fmaf(h[4], -e[d+2], s1);
            s1 = fmaf(h[3], o[d+2], s1);
            s1 = fmaf(h[2], -e[d+3], s1);
            s1 = fmaf(h[1], o[d+3], s1);
            s1 = fmaf(h[0], -e[d+4], s1);
            hi[d] = s1;
        }

        lo4[t] = make_float4(lo[0], lo[1], lo[2], lo[3]);
        hi4[t] = make_float4(hi[0], hi[1], hi[2], hi[3]);
    }
}

extern "C" void kernel_launch(void* const* d_in, const int* in_sizes, int n_in,
                              void* d_out, int out_size)
{
    const float4* x  = (const float4*)d_in[0];
    const float* mlo = (const float*)d_in[1];
    const float* mhi = (const float*)d_in[2];
    float* out = (float*)d_out;

    dwt1d_kernel<<<NC * 2, TPB>>>(x, mlo, mhi, out);
}